// round 3
// baseline (speedup 1.0000x reference)
#include <cuda_runtime.h>
#include <cuda_bf16.h>
#include <stdint.h>

#define D 256
#define NC 32
#define NH 4
#define C1C 1152
#define NMAX 16384

// ---------------- static device scratch (no allocation allowed) --------------
__device__ float         g_Af32[NH * 256 * 256];   // scaled A_h fp32
__device__ float         g_Bf32[1024 * 256];       // Bv fp32
__device__ __nv_bfloat16 g_Abf[256 * C1C];         // GEMM1 weights [256][1152]
__device__ __nv_bfloat16 g_Bbf[C1C * 256];         // GEMM2 weights [1152][256]
__device__ __nv_bfloat16 g_C1[(size_t)NMAX * C1C]; // GEMM1 out (qW|qP)
__device__ __nv_bfloat16 g_U [(size_t)NMAX * C1C]; // attention out (u|pw)
__device__ float         g_X [(size_t)NMAX * D];   // pre-LN x
__device__ int           g_is64;

// ---------------- helpers ----------------------------------------------------
__device__ __forceinline__ unsigned smaddr(const void* p) {
    return (unsigned)__cvta_generic_to_shared(p);
}
__device__ __forceinline__ void ldsm4(uint32_t* r, unsigned a) {
    asm volatile("ldmatrix.sync.aligned.m8n8.x4.shared.b16 {%0,%1,%2,%3}, [%4];"
                 : "=r"(r[0]), "=r"(r[1]), "=r"(r[2]), "=r"(r[3]) : "r"(a));
}
__device__ __forceinline__ void ldsm4t(uint32_t* r, unsigned a) {
    asm volatile("ldmatrix.sync.aligned.m8n8.x4.trans.shared.b16 {%0,%1,%2,%3}, [%4];"
                 : "=r"(r[0]), "=r"(r[1]), "=r"(r[2]), "=r"(r[3]) : "r"(a));
}
__device__ __forceinline__ void mma16816(float* c, const uint32_t* a, const uint32_t* b) {
    asm volatile(
        "mma.sync.aligned.m16n8k16.row.col.f32.bf16.bf16.f32 "
        "{%0,%1,%2,%3},{%4,%5,%6,%7},{%8,%9},{%0,%1,%2,%3};"
        : "+f"(c[0]), "+f"(c[1]), "+f"(c[2]), "+f"(c[3])
        : "r"(a[0]), "r"(a[1]), "r"(a[2]), "r"(a[3]), "r"(b[0]), "r"(b[1]));
}

// ---------------- idx dtype detection (int64 vs int32) -----------------------
__global__ void pk_detect(const unsigned* __restrict__ idx) {
    __shared__ int any;
    if (threadIdx.x == 0) any = 0;
    __syncthreads();
    if (idx[2 * threadIdx.x + 1] != 0u) any = 1; // benign race
    __syncthreads();
    if (threadIdx.x == 0) g_is64 = any ? 0 : 1;
}

// ---------------- precompute -------------------------------------------------
// A_h[i,j] = (1/8) * sum_dk Wkv[h*64+dk, j] * Wq[h*64+dk, i]
__global__ void pk1(const float* __restrict__ Wq, const float* __restrict__ Wkv) {
    int h = blockIdx.x >> 8, j = blockIdx.x & 255, i = threadIdx.x;
    __shared__ float wk[64];
    if (i < 64) wk[i] = Wkv[(h * 64 + i) * 256 + j];
    __syncthreads();
    float acc = 0.f;
#pragma unroll 8
    for (int dk = 0; dk < 64; dk++) acc += wk[dk] * Wq[(h * 64 + dk) * 256 + i];
    acc *= 0.125f;
    g_Af32[(h * 256 + j) * 256 + i] = acc;
    g_Abf[i * C1C + h * 256 + j] = __float2bfloat16_rn(acc);
}
// qP columns: Abf[i, 1024+h*32+c] = sum_j A_h[i,j] * pos[c,j]
__global__ void pk2(const float* __restrict__ pos) {
    int h = blockIdx.x >> 5, c = blockIdx.x & 31, i = threadIdx.x;
    __shared__ float pe[256];
    pe[i] = pos[c * 256 + i];
    __syncthreads();
    float acc = 0.f;
#pragma unroll 4
    for (int j = 0; j < 256; j++) acc += g_Af32[(h * 256 + j) * 256 + i] * pe[j];
    g_Abf[i * C1C + 1024 + h * 32 + c] = __float2bfloat16_rn(acc);
}
// Bv_h[j,o] = sum_dk Wout[o, h*64+dk] * Wkv[256+h*64+dk, j]
__global__ void pk3(const float* __restrict__ Wout, const float* __restrict__ Wkv) {
    int o = blockIdx.x, j = threadIdx.x;
    __shared__ float wo[256];
    wo[j] = Wout[o * 256 + j];
    __syncthreads();
    for (int h = 0; h < NH; h++) {
        float acc = 0.f;
#pragma unroll 8
        for (int dk = 0; dk < 64; dk++)
            acc += wo[h * 64 + dk] * Wkv[(256 + h * 64 + dk) * 256 + j];
        g_Bf32[(h * 256 + j) * 256 + o] = acc;
        g_Bbf[(h * 256 + j) * 256 + o] = __float2bfloat16_rn(acc);
    }
}
// pos rows: Bbf[1024+h*32+c, o] = sum_j pos[c,j] * Bv_h[j,o]
__global__ void pk4(const float* __restrict__ pos) {
    int h = blockIdx.x >> 5, c = blockIdx.x & 31, o = threadIdx.x;
    __shared__ float pe[256];
    pe[o] = pos[c * 256 + o];
    __syncthreads();
    float acc = 0.f;
#pragma unroll 4
    for (int j = 0; j < 256; j++) acc += pe[j] * g_Bf32[(h * 256 + j) * 256 + o];
    g_Bbf[(1024 + h * 32 + c) * 256 + o] = __float2bfloat16_rn(acc);
}

// ---------------- GEMM (128x128 tile, bf16 mma.sync) -------------------------
// MODE 0: C1[N,1152] = bf16(parent[N,256]) @ g_Abf ; store bf16 g_C1
// MODE 1: x[N,256]   = g_U[N,1152] @ g_Bbf + bout + parent ; store fp32 g_X
template <int MODE>
__global__ __launch_bounds__(256) void gemm_k(const float* __restrict__ Af,
                                              const float* __restrict__ parent,
                                              const float* __restrict__ bias) {
    constexpr int KT = MODE ? C1C : 256;
    constexpr int NT = MODE ? 256 : C1C;
    __shared__ __nv_bfloat16 Asm[128][72];
    __shared__ __nv_bfloat16 Bsm[64][136];
    int t = threadIdx.x, lane = t & 31, warp = t >> 5;
    int m0 = blockIdx.x * 128, n0 = blockIdx.y * 128;
    int wm = (warp >> 2) * 64, wn = (warp & 3) * 32;
    float acc[4][4][4];
#pragma unroll
    for (int a = 0; a < 4; a++)
#pragma unroll
        for (int b = 0; b < 4; b++)
#pragma unroll
            for (int c = 0; c < 4; c++) acc[a][b][c] = 0.f;
    const __nv_bfloat16* Bg = MODE ? g_Bbf : g_Abf;

    for (int kc = 0; kc < KT / 64; kc++) {
        if (MODE == 0) {
#pragma unroll
            for (int it = 0; it < 8; it++) {
                int lin = it * 256 + t, r = lin >> 4, c4 = lin & 15;
                float4 v = *(const float4*)(Af + (size_t)(m0 + r) * KT + kc * 64 + c4 * 4);
                __nv_bfloat162* dp = (__nv_bfloat162*)&Asm[r][c4 * 4];
                dp[0] = __floats2bfloat162_rn(v.x, v.y);
                dp[1] = __floats2bfloat162_rn(v.z, v.w);
            }
        } else {
#pragma unroll
            for (int it = 0; it < 4; it++) {
                int lin = it * 256 + t, r = lin >> 3, c8 = lin & 7;
                *(uint4*)&Asm[r][c8 * 8] =
                    *(const uint4*)(g_U + (size_t)(m0 + r) * KT + kc * 64 + c8 * 8);
            }
        }
#pragma unroll
        for (int it = 0; it < 4; it++) {
            int lin = it * 256 + t, r = lin >> 4, c8 = lin & 15;
            *(uint4*)&Bsm[r][c8 * 8] =
                *(const uint4*)(Bg + (size_t)(kc * 64 + r) * NT + n0 + c8 * 8);
        }
        __syncthreads();
#pragma unroll
        for (int ks = 0; ks < 4; ks++) {
            uint32_t af[4][4], bf[2][4];
#pragma unroll
            for (int mi = 0; mi < 4; mi++)
                ldsm4(af[mi], smaddr(&Asm[wm + mi * 16 + (lane & 15)][ks * 16 + (lane >> 4) * 8]));
#pragma unroll
            for (int nj = 0; nj < 2; nj++)
                ldsm4t(bf[nj], smaddr(&Bsm[ks * 16 + (lane & 15)][wn + nj * 16 + (lane >> 4) * 8]));
#pragma unroll
            for (int mi = 0; mi < 4; mi++)
#pragma unroll
                for (int nn = 0; nn < 4; nn++)
                    mma16816(acc[mi][nn], af[mi], &bf[nn >> 1][(nn & 1) * 2]);
        }
        __syncthreads();
    }
#pragma unroll
    for (int mi = 0; mi < 4; mi++)
#pragma unroll
        for (int nn = 0; nn < 4; nn++) {
            int r = m0 + wm + mi * 16 + (lane >> 2);
            int c = n0 + wn + nn * 8 + (lane & 3) * 2;
            float* a = acc[mi][nn];
            if (MODE == 0) {
                *(__nv_bfloat162*)&g_C1[(size_t)r * C1C + c] = __floats2bfloat162_rn(a[0], a[1]);
                *(__nv_bfloat162*)&g_C1[(size_t)(r + 8) * C1C + c] = __floats2bfloat162_rn(a[2], a[3]);
            } else {
                float b0 = bias[c], b1 = bias[c + 1];
                float2 p0 = *(const float2*)(parent + (size_t)r * D + c);
                float2 p1 = *(const float2*)(parent + (size_t)(r + 8) * D + c);
                *(float2*)&g_X[(size_t)r * D + c] = make_float2(a[0] + b0 + p0.x, a[1] + b1 + p0.y);
                *(float2*)&g_X[(size_t)(r + 8) * D + c] = make_float2(a[2] + b0 + p1.x, a[3] + b1 + p1.y);
            }
        }
}

// ---------------- attention kernel (one block per row) -----------------------
__global__ __launch_bounds__(256) void attn_k(const float* __restrict__ child,
                                              const unsigned* __restrict__ idx) {
    __shared__ float  chT[256][33];   // child transposed [d][n]
    __shared__ float4 qw4s[256];      // qwT[d][h] as float4 per d
    __shared__ float  qp[128];
    __shared__ float4 att4s[32];      // scores/att [n][h]
    __shared__ float  pw[128];
    __shared__ int    idxs[32];
    __shared__ float4 part4[256];     // phase-1 partials [rep][n]

    float* qwT = (float*)qw4s;
    float* sc  = (float*)att4s;
    float* part = (float*)part4;
    int b = blockIdx.x, t = threadIdx.x;

    // loads
    if (t < 32) {
        unsigned raw = g_is64 ? idx[(size_t)(b * 32 + t) * 2] : idx[b * 32 + t];
        idxs[t] = (int)(raw & 31u);
    }
    if (t < 128) {
        pw[t] = 0.f;
        qp[t] = __bfloat162float(g_C1[(size_t)b * C1C + 1024 + t]);
    }
#pragma unroll
    for (int k = 0; k < 4; k++)
        qwT[t * 4 + k] = __bfloat162float(g_C1[(size_t)b * C1C + k * 256 + t]);
    const float4* cf4 = (const float4*)(child + (size_t)b * NC * D);
#pragma unroll
    for (int it = 0; it < 8; it++) {
        int lin = it * 256 + t, n = lin >> 6, d4 = lin & 63;
        float4 v = cf4[n * 64 + d4];
        chT[4 * d4 + 0][n] = v.x; chT[4 * d4 + 1][n] = v.y;
        chT[4 * d4 + 2][n] = v.z; chT[4 * d4 + 3][n] = v.w;
    }
    __syncthreads();

    // phase 1: partial scores. thread (rep = warp, n = lane) covers d in [rep*32, rep*32+32)
    {
        int rep = t >> 5, n = t & 31;
        float a0 = 0.f, a1 = 0.f, a2 = 0.f, a3 = 0.f;
#pragma unroll 8
        for (int i = 0; i < 32; i++) {
            int d = rep * 32 + i;
            float c = chT[d][n];
            float4 q = qw4s[d];
            a0 += c * q.x; a1 += c * q.y; a2 += c * q.z; a3 += c * q.w;
        }
        part4[rep * 32 + n] = make_float4(a0, a1, a2, a3);
    }
    __syncthreads();
    // reduce partials + pos bias
    if (t < 128) {
        int n = t >> 2, h = t & 3;
        float s = 0.f;
#pragma unroll
        for (int rep = 0; rep < 8; rep++) s += part[(rep * 32 + n) * 4 + h];
        sc[n * 4 + h] = s + qp[h * 32 + idxs[n]];
    }
    __syncthreads();
    // phase 2: softmax over n per head (warp h, lane n) + pw scatter
    if (t < 128) {
        int h = t >> 5, n = t & 31;
        float s = sc[n * 4 + h];
        float m = s;
#pragma unroll
        for (int o = 16; o > 0; o >>= 1) m = fmaxf(m, __shfl_xor_sync(0xffffffffu, m, o));
        float e = __expf(s - m);
        float su = e;
#pragma unroll
        for (int o = 16; o > 0; o >>= 1) su += __shfl_xor_sync(0xffffffffu, su, o);
        float a = e / su;
        sc[n * 4 + h] = a;
        atomicAdd(&pw[h * 32 + idxs[n]], a);
    }
    __syncthreads();
    // phase 3: u[h][d] = sum_n att[n][h] * child[n][d]  (thread = d)
    {
        int d = t;
        float u0 = 0.f, u1 = 0.f, u2 = 0.f, u3 = 0.f;
#pragma unroll 8
        for (int n = 0; n < 32; n++) {
            float c = chT[d][n];
            float4 a = att4s[n];
            u0 += c * a.x; u1 += c * a.y; u2 += c * a.z; u3 += c * a.w;
        }
        __nv_bfloat16* Ub = g_U + (size_t)b * C1C;
        Ub[0 * 256 + d] = __float2bfloat16_rn(u0);
        Ub[1 * 256 + d] = __float2bfloat16_rn(u1);
        Ub[2 * 256 + d] = __float2bfloat16_rn(u2);
        Ub[3 * 256 + d] = __float2bfloat16_rn(u3);
        if (t < 128) Ub[1024 + t] = __float2bfloat16_rn(pw[t]);
    }
}

// ---------------- LayerNorm --------------------------------------------------
__global__ __launch_bounds__(256) void ln_k(const float* __restrict__ gamma,
                                            const float* __restrict__ beta,
                                            float* __restrict__ out) {
    int w = threadIdx.x >> 5, lane = threadIdx.x & 31;
    size_t b = (size_t)blockIdx.x * 8 + w;
    const float4* xp = (const float4*)(g_X + b * D);
    float4 v0 = xp[lane], v1 = xp[lane + 32];
    float s  = v0.x + v0.y + v0.z + v0.w + v1.x + v1.y + v1.z + v1.w;
    float ss = v0.x * v0.x + v0.y * v0.y + v0.z * v0.z + v0.w * v0.w +
               v1.x * v1.x + v1.y * v1.y + v1.z * v1.z + v1.w * v1.w;
#pragma unroll
    for (int o = 16; o > 0; o >>= 1) {
        s  += __shfl_xor_sync(0xffffffffu, s, o);
        ss += __shfl_xor_sync(0xffffffffu, ss, o);
    }
    float mu = s * (1.0f / 256.0f);
    float var = ss * (1.0f / 256.0f) - mu * mu;
    float rs = rsqrtf(var + 1e-5f);
    float4 g0 = ((const float4*)gamma)[lane], g1 = ((const float4*)gamma)[lane + 32];
    float4 b0 = ((const float4*)beta)[lane],  b1 = ((const float4*)beta)[lane + 32];
    float4* op = (float4*)(out + b * D);
    op[lane] = make_float4((v0.x - mu) * rs * g0.x + b0.x, (v0.y - mu) * rs * g0.y + b0.y,
                           (v0.z - mu) * rs * g0.z + b0.z, (v0.w - mu) * rs * g0.w + b0.w);
    op[lane + 32] = make_float4((v1.x - mu) * rs * g1.x + b1.x, (v1.y - mu) * rs * g1.y + b1.y,
                                (v1.z - mu) * rs * g1.z + b1.z, (v1.w - mu) * rs * g1.w + b1.w);
}

// ---------------- launch -----------------------------------------------------
extern "C" void kernel_launch(void* const* d_in, const int* in_sizes, int n_in,
                              void* d_out, int out_size) {
    const float*    parent = (const float*)d_in[0];
    const float*    child  = (const float*)d_in[1];
    const unsigned* idx    = (const unsigned*)d_in[2];
    const float*    Wq     = (const float*)d_in[3];
    const float*    Wkv    = (const float*)d_in[4];
    const float*    pos    = (const float*)d_in[5];
    const float*    Wout   = (const float*)d_in[6];
    const float*    bout   = (const float*)d_in[7];
    const float*    gamma  = (const float*)d_in[8];
    const float*    beta   = (const float*)d_in[9];
    float* out = (float*)d_out;
    int N = in_sizes[0] / D;

    pk_detect<<<1, 64>>>(idx);
    pk1<<<NH * 256, 256>>>(Wq, Wkv);
    pk2<<<NH * NC, 256>>>(pos);
    pk3<<<256, 256>>>(Wout, Wkv);
    pk4<<<NH * NC, 256>>>(pos);
    gemm_k<0><<<dim3(N / 128, 9), 256>>>(parent, nullptr, nullptr);
    attn_k<<<N, 256>>>(child, idx);
    gemm_k<1><<<dim3(N / 128, 2), 256>>>(nullptr, parent, bout);
    ln_k<<<N / 8, 256>>>(gamma, beta, out);
}

// round 4
// speedup vs baseline: 1.0311x; 1.0311x over previous
#include <cuda_runtime.h>
#include <cuda_bf16.h>
#include <stdint.h>

#define D 256
#define NC 32
#define NH 4
#define C1C 1152
#define NMAX 16384

// ---------------- static device scratch (no allocation allowed) --------------
__device__ float         g_Af32[NH * 256 * 256];   // scaled A_h fp32  [hj][i]
__device__ float         g_Bf32[1024 * 256];       // Bv fp32          [hj][o]
__device__ float         g_WoT [256 * 256];        // Wout^T           [j][o]
__device__ __nv_bfloat16 g_Abf[256 * C1C];         // GEMM1 weights [K=256][1152]
__device__ __nv_bfloat16 g_Bbf[C1C * 256];         // GEMM2 weights [K=1152][256]
__device__ __nv_bfloat16 g_Pbf[(size_t)NMAX * D];  // parent in bf16
__device__ __nv_bfloat16 g_C1[(size_t)NMAX * C1C]; // GEMM1 out (qW|qP)
__device__ __nv_bfloat16 g_U [(size_t)NMAX * C1C]; // attention out (u|pw)
__device__ float         g_X [(size_t)NMAX * D];   // pre-LN x
__device__ int           g_is64;

// ---------------- helpers ----------------------------------------------------
__device__ __forceinline__ unsigned smaddr(const void* p) {
    return (unsigned)__cvta_generic_to_shared(p);
}
__device__ __forceinline__ void ldsm4(uint32_t* r, unsigned a) {
    asm volatile("ldmatrix.sync.aligned.m8n8.x4.shared.b16 {%0,%1,%2,%3}, [%4];"
                 : "=r"(r[0]), "=r"(r[1]), "=r"(r[2]), "=r"(r[3]) : "r"(a));
}
__device__ __forceinline__ void ldsm4t(uint32_t* r, unsigned a) {
    asm volatile("ldmatrix.sync.aligned.m8n8.x4.trans.shared.b16 {%0,%1,%2,%3}, [%4];"
                 : "=r"(r[0]), "=r"(r[1]), "=r"(r[2]), "=r"(r[3]) : "r"(a));
}
__device__ __forceinline__ void mma16816(float* c, const uint32_t* a, const uint32_t* b) {
    asm volatile(
        "mma.sync.aligned.m16n8k16.row.col.f32.bf16.bf16.f32 "
        "{%0,%1,%2,%3},{%4,%5,%6,%7},{%8,%9},{%0,%1,%2,%3};"
        : "+f"(c[0]), "+f"(c[1]), "+f"(c[2]), "+f"(c[3])
        : "r"(a[0]), "r"(a[1]), "r"(a[2]), "r"(a[3]), "r"(b[0]), "r"(b[1]));
}

// ---------------- idx dtype detection (int64 vs int32) -----------------------
__global__ void pk_detect(const unsigned* __restrict__ idx) {
    __shared__ int any;
    if (threadIdx.x == 0) any = 0;
    __syncthreads();
    if (idx[2 * threadIdx.x + 1] != 0u) any = 1; // benign race
    __syncthreads();
    if (threadIdx.x == 0) g_is64 = any ? 0 : 1;
}

// ---------------- precompute -------------------------------------------------
// Wout^T (coalesced both ways via smem tile)
__global__ __launch_bounds__(256) void pk_wot(const float* __restrict__ W) {
    __shared__ float tl[32][33];
    int x0 = blockIdx.x * 32, y0 = blockIdx.y * 32;
    int tx = threadIdx.x & 31, ty = threadIdx.x >> 5;
#pragma unroll
    for (int k = 0; k < 4; k++) tl[ty + 8 * k][tx] = W[(y0 + ty + 8 * k) * 256 + x0 + tx];
    __syncthreads();
#pragma unroll
    for (int k = 0; k < 4; k++) g_WoT[(x0 + ty + 8 * k) * 256 + y0 + tx] = tl[tx][ty + 8 * k];
}

// A_h[i,j] = (1/8) * sum_dk Wkv[h*64+dk, j] * Wq[h*64+dk, i]   (fp32 only, coalesced)
__global__ __launch_bounds__(256) void pk1(const float* __restrict__ Wq,
                                           const float* __restrict__ Wkv) {
    int h = blockIdx.x >> 8, j = blockIdx.x & 255, i = threadIdx.x;
    __shared__ float wk[64];
    if (i < 64) wk[i] = Wkv[(h * 64 + i) * 256 + j];
    __syncthreads();
    float acc = 0.f;
#pragma unroll 8
    for (int dk = 0; dk < 64; dk++) acc += wk[dk] * Wq[(h * 64 + dk) * 256 + i];
    g_Af32[(h * 256 + j) * 256 + i] = acc * 0.125f;
}
// pack: g_Abf[i][hj] = bf16(g_Af32[hj][i])  — smem-tile transpose
__global__ __launch_bounds__(256) void pk_pack() {
    __shared__ float tl[32][33];
    int hj0 = blockIdx.x * 32, i0 = blockIdx.y * 32;
    int tx = threadIdx.x & 31, ty = threadIdx.x >> 5;
#pragma unroll
    for (int k = 0; k < 4; k++) tl[ty + 8 * k][tx] = g_Af32[(hj0 + ty + 8 * k) * 256 + i0 + tx];
    __syncthreads();
#pragma unroll
    for (int k = 0; k < 4; k++)
        g_Abf[(size_t)(i0 + ty + 8 * k) * C1C + hj0 + tx] = __float2bfloat16_rn(tl[tx][ty + 8 * k]);
}
// qP columns: Abf[i, 1024+h*32+c] = sum_j A_h[i,j] * pos[c,j]
__global__ __launch_bounds__(256) void pk2(const float* __restrict__ pos) {
    int h = blockIdx.x >> 5, c = blockIdx.x & 31, i = threadIdx.x;
    __shared__ float pe[256];
    pe[i] = pos[c * 256 + i];
    __syncthreads();
    float acc = 0.f;
#pragma unroll 8
    for (int j = 0; j < 256; j++) acc += g_Af32[(h * 256 + j) * 256 + i] * pe[j];
    g_Abf[(size_t)i * C1C + 1024 + h * 32 + c] = __float2bfloat16_rn(acc);
}
// Bv[hj][o] = sum_dk WoT[h*64+dk][o] * Wkv[256+h*64+dk][j]   (all coalesced)
__global__ __launch_bounds__(256) void pk3(const float* __restrict__ Wkv) {
    int h = blockIdx.x >> 8, j = blockIdx.x & 255, o = threadIdx.x;
    __shared__ float wk[64];
    if (o < 64) wk[o] = Wkv[(256 + h * 64 + o) * 256 + j];
    __syncthreads();
    float acc = 0.f;
#pragma unroll 8
    for (int dk = 0; dk < 64; dk++) acc += g_WoT[(h * 64 + dk) * 256 + o] * wk[dk];
    g_Bf32[(h * 256 + j) * 256 + o] = acc;
    g_Bbf[(size_t)(h * 256 + j) * 256 + o] = __float2bfloat16_rn(acc);
}
// pos rows: Bbf[1024+h*32+c, o] = sum_j pos[c,j] * Bv[hj][o]
__global__ __launch_bounds__(256) void pk4(const float* __restrict__ pos) {
    int h = blockIdx.x >> 5, c = blockIdx.x & 31, o = threadIdx.x;
    __shared__ float pe[256];
    pe[o] = pos[c * 256 + o];
    __syncthreads();
    float acc = 0.f;
#pragma unroll 8
    for (int j = 0; j < 256; j++) acc += pe[j] * g_Bf32[(h * 256 + j) * 256 + o];
    g_Bbf[(size_t)(1024 + h * 32 + c) * 256 + o] = __float2bfloat16_rn(acc);
}
// parent fp32 -> bf16
__global__ __launch_bounds__(256) void pk_par(const float* __restrict__ p) {
    int i = blockIdx.x * 256 + threadIdx.x;
    float4 a = ((const float4*)p)[2 * i], b = ((const float4*)p)[2 * i + 1];
    union { __nv_bfloat162 h[4]; uint4 v; } u;
    u.h[0] = __floats2bfloat162_rn(a.x, a.y);
    u.h[1] = __floats2bfloat162_rn(a.z, a.w);
    u.h[2] = __floats2bfloat162_rn(b.x, b.y);
    u.h[3] = __floats2bfloat162_rn(b.z, b.w);
    ((uint4*)g_Pbf)[i] = u.v;
}

// ---------------- GEMM (64x128 tile, bf16 mma.sync, reg-prefetch) ------------
// MODE 0: C1[N,1152] = g_Pbf[N,256] @ g_Abf ; store bf16 g_C1
// MODE 1: x[N,256]   = g_U[N,1152] @ g_Bbf + bout + parent ; store fp32 g_X
template <int MODE>
__global__ __launch_bounds__(256) void gemm_k(const float* __restrict__ parent,
                                              const float* __restrict__ bias) {
    constexpr int KT = MODE ? C1C : 256;
    constexpr int NT = MODE ? 256 : C1C;
    constexpr int NCH = KT / 64;
    __shared__ __nv_bfloat16 Asm[64][72];
    __shared__ __nv_bfloat16 Bsm[64][136];
    int t = threadIdx.x, lane = t & 31, warp = t >> 5;
    int m0 = blockIdx.x * 64, n0 = blockIdx.y * 128;
    int wm = (warp >> 2) * 32, wn = (warp & 3) * 32;
    const __nv_bfloat16* Ag = MODE ? g_U : g_Pbf;
    const __nv_bfloat16* Bg = MODE ? g_Bbf : g_Abf;

    float acc[2][4][4];
#pragma unroll
    for (int a = 0; a < 2; a++)
#pragma unroll
        for (int b = 0; b < 4; b++)
#pragma unroll
            for (int c = 0; c < 4; c++) acc[a][b][c] = 0.f;

    uint4 pa[2], pb[4];
#pragma unroll
    for (int it = 0; it < 2; it++) {
        int lin = it * 256 + t, r = lin >> 3, c8 = lin & 7;
        pa[it] = *(const uint4*)(Ag + (size_t)(m0 + r) * KT + c8 * 8);
    }
#pragma unroll
    for (int it = 0; it < 4; it++) {
        int lin = it * 256 + t, r = lin >> 4, c8 = lin & 15;
        pb[it] = *(const uint4*)(Bg + (size_t)r * NT + n0 + c8 * 8);
    }

    for (int kc = 0; kc < NCH; kc++) {
#pragma unroll
        for (int it = 0; it < 2; it++) {
            int lin = it * 256 + t, r = lin >> 3, c8 = lin & 7;
            *(uint4*)&Asm[r][c8 * 8] = pa[it];
        }
#pragma unroll
        for (int it = 0; it < 4; it++) {
            int lin = it * 256 + t, r = lin >> 4, c8 = lin & 15;
            *(uint4*)&Bsm[r][c8 * 8] = pb[it];
        }
        __syncthreads();
        if (kc + 1 < NCH) {
#pragma unroll
            for (int it = 0; it < 2; it++) {
                int lin = it * 256 + t, r = lin >> 3, c8 = lin & 7;
                pa[it] = *(const uint4*)(Ag + (size_t)(m0 + r) * KT + (kc + 1) * 64 + c8 * 8);
            }
#pragma unroll
            for (int it = 0; it < 4; it++) {
                int lin = it * 256 + t, r = lin >> 4, c8 = lin & 15;
                pb[it] = *(const uint4*)(Bg + (size_t)((kc + 1) * 64 + r) * NT + n0 + c8 * 8);
            }
        }
#pragma unroll
        for (int ks = 0; ks < 4; ks++) {
            uint32_t af[2][4], bfr[2][4];
#pragma unroll
            for (int mi = 0; mi < 2; mi++)
                ldsm4(af[mi], smaddr(&Asm[wm + mi * 16 + (lane & 15)][ks * 16 + (lane >> 4) * 8]));
#pragma unroll
            for (int nj = 0; nj < 2; nj++)
                ldsm4t(bfr[nj], smaddr(&Bsm[ks * 16 + (lane & 15)][wn + nj * 16 + (lane >> 4) * 8]));
#pragma unroll
            for (int mi = 0; mi < 2; mi++)
#pragma unroll
                for (int nn = 0; nn < 4; nn++)
                    mma16816(acc[mi][nn], af[mi], &bfr[nn >> 1][(nn & 1) * 2]);
        }
        __syncthreads();
    }
#pragma unroll
    for (int mi = 0; mi < 2; mi++)
#pragma unroll
        for (int nn = 0; nn < 4; nn++) {
            int r = m0 + wm + mi * 16 + (lane >> 2);
            int c = n0 + wn + nn * 8 + (lane & 3) * 2;
            float* a = acc[mi][nn];
            if (MODE == 0) {
                *(__nv_bfloat162*)&g_C1[(size_t)r * C1C + c] = __floats2bfloat162_rn(a[0], a[1]);
                *(__nv_bfloat162*)&g_C1[(size_t)(r + 8) * C1C + c] = __floats2bfloat162_rn(a[2], a[3]);
            } else {
                float b0 = bias[c], b1 = bias[c + 1];
                float2 p0 = *(const float2*)(parent + (size_t)r * D + c);
                float2 p1 = *(const float2*)(parent + (size_t)(r + 8) * D + c);
                *(float2*)&g_X[(size_t)r * D + c] = make_float2(a[0] + b0 + p0.x, a[1] + b1 + p0.y);
                *(float2*)&g_X[(size_t)(r + 8) * D + c] = make_float2(a[2] + b0 + p1.x, a[3] + b1 + p1.y);
            }
        }
}

// ---------------- attention kernel (one block per row) -----------------------
__global__ __launch_bounds__(256) void attn_k(const float* __restrict__ child,
                                              const unsigned* __restrict__ idx) {
    __shared__ float  chT[256][33];   // child transposed [d][n]
    __shared__ float4 qw4s[256];      // qwT[d][h]
    __shared__ float  qp[128];
    __shared__ float4 att4s[32];      // scores/att [n][h]
    __shared__ float  pw[128];
    __shared__ int    idxs[32];
    __shared__ float4 part4[256];     // phase-1 partials [rep][n]

    float* qwT = (float*)qw4s;
    float* sc  = (float*)att4s;
    float* part = (float*)part4;
    int b = blockIdx.x, t = threadIdx.x;

    if (t < 32) {
        unsigned raw = g_is64 ? idx[(size_t)(b * 32 + t) * 2] : idx[b * 32 + t];
        idxs[t] = (int)(raw & 31u);
    }
    if (t < 128) {
        pw[t] = 0.f;
        qp[t] = __bfloat162float(g_C1[(size_t)b * C1C + 1024 + t]);
    }
#pragma unroll
    for (int k = 0; k < 4; k++)
        qwT[t * 4 + k] = __bfloat162float(g_C1[(size_t)b * C1C + k * 256 + t]);
    const float4* cf4 = (const float4*)(child + (size_t)b * NC * D);
#pragma unroll
    for (int it = 0; it < 8; it++) {
        int lin = it * 256 + t, n = lin >> 6, d4 = lin & 63;
        float4 v = __ldcs(cf4 + n * 64 + d4);   // streaming: read-once data
        chT[4 * d4 + 0][n] = v.x; chT[4 * d4 + 1][n] = v.y;
        chT[4 * d4 + 2][n] = v.z; chT[4 * d4 + 3][n] = v.w;
    }
    __syncthreads();

    // phase 1: partial scores (warp=rep over d-range, lane=n)
    {
        int rep = t >> 5, n = t & 31;
        float a0 = 0.f, a1 = 0.f, a2 = 0.f, a3 = 0.f;
#pragma unroll 8
        for (int i = 0; i < 32; i++) {
            int d = rep * 32 + i;
            float c = chT[d][n];
            float4 q = qw4s[d];
            a0 += c * q.x; a1 += c * q.y; a2 += c * q.z; a3 += c * q.w;
        }
        part4[rep * 32 + n] = make_float4(a0, a1, a2, a3);
    }
    __syncthreads();
    if (t < 128) {
        int n = t >> 2, h = t & 3;
        float s = 0.f;
#pragma unroll
        for (int rep = 0; rep < 8; rep++) s += part[(rep * 32 + n) * 4 + h];
        sc[n * 4 + h] = s + qp[h * 32 + idxs[n]];
    }
    __syncthreads();
    // phase 2: softmax over n per head (warp h, lane n) + pw scatter
    if (t < 128) {
        int h = t >> 5, n = t & 31;
        float s = sc[n * 4 + h];
        float m = s;
#pragma unroll
        for (int o = 16; o > 0; o >>= 1) m = fmaxf(m, __shfl_xor_sync(0xffffffffu, m, o));
        float e = __expf(s - m);
        float su = e;
#pragma unroll
        for (int o = 16; o > 0; o >>= 1) su += __shfl_xor_sync(0xffffffffu, su, o);
        float a = e / su;
        sc[n * 4 + h] = a;
        atomicAdd(&pw[h * 32 + idxs[n]], a);
    }
    __syncthreads();
    // phase 3: u[h][d] = sum_n att[n][h] * child[n][d]  (thread = d)
    {
        int d = t;
        float u0 = 0.f, u1 = 0.f, u2 = 0.f, u3 = 0.f;
#pragma unroll 8
        for (int n = 0; n < 32; n++) {
            float c = chT[d][n];
            float4 a = att4s[n];
            u0 += c * a.x; u1 += c * a.y; u2 += c * a.z; u3 += c * a.w;
        }
        __nv_bfloat16* Ub = g_U + (size_t)b * C1C;
        Ub[0 * 256 + d] = __float2bfloat16_rn(u0);
        Ub[1 * 256 + d] = __float2bfloat16_rn(u1);
        Ub[2 * 256 + d] = __float2bfloat16_rn(u2);
        Ub[3 * 256 + d] = __float2bfloat16_rn(u3);
        if (t < 128) Ub[1024 + t] = __float2bfloat16_rn(pw[t]);
    }
}

// ---------------- LayerNorm --------------------------------------------------
__global__ __launch_bounds__(256) void ln_k(const float* __restrict__ gamma,
                                            const float* __restrict__ beta,
                                            float* __restrict__ out) {
    int w = threadIdx.x >> 5, lane = threadIdx.x & 31;
    size_t b = (size_t)blockIdx.x * 8 + w;
    const float4* xp = (const float4*)(g_X + b * D);
    float4 v0 = xp[lane], v1 = xp[lane + 32];
    float s  = v0.x + v0.y + v0.z + v0.w + v1.x + v1.y + v1.z + v1.w;
    float ss = v0.x * v0.x + v0.y * v0.y + v0.z * v0.z + v0.w * v0.w +
               v1.x * v1.x + v1.y * v1.y + v1.z * v1.z + v1.w * v1.w;
#pragma unroll
    for (int o = 16; o > 0; o >>= 1) {
        s  += __shfl_xor_sync(0xffffffffu, s, o);
        ss += __shfl_xor_sync(0xffffffffu, ss, o);
    }
    float mu = s * (1.0f / 256.0f);
    float var = ss * (1.0f / 256.0f) - mu * mu;
    float rs = rsqrtf(var + 1e-5f);
    float4 g0 = ((const float4*)gamma)[lane], g1 = ((const float4*)gamma)[lane + 32];
    float4 b0 = ((const float4*)beta)[lane],  b1 = ((const float4*)beta)[lane + 32];
    float4* op = (float4*)(out + b * D);
    op[lane] = make_float4((v0.x - mu) * rs * g0.x + b0.x, (v0.y - mu) * rs * g0.y + b0.y,
                           (v0.z - mu) * rs * g0.z + b0.z, (v0.w - mu) * rs * g0.w + b0.w);
    op[lane + 32] = make_float4((v1.x - mu) * rs * g1.x + b1.x, (v1.y - mu) * rs * g1.y + b1.y,
                                (v1.z - mu) * rs * g1.z + b1.z, (v1.w - mu) * rs * g1.w + b1.w);
}

// ---------------- launch -----------------------------------------------------
extern "C" void kernel_launch(void* const* d_in, const int* in_sizes, int n_in,
                              void* d_out, int out_size) {
    const float*    parent = (const float*)d_in[0];
    const float*    child  = (const float*)d_in[1];
    const unsigned* idx    = (const unsigned*)d_in[2];
    const float*    Wq     = (const float*)d_in[3];
    const float*    Wkv    = (const float*)d_in[4];
    const float*    pos    = (const float*)d_in[5];
    const float*    Wout   = (const float*)d_in[6];
    const float*    bout   = (const float*)d_in[7];
    const float*    gamma  = (const float*)d_in[8];
    const float*    beta   = (const float*)d_in[9];
    float* out = (float*)d_out;
    int N = in_sizes[0] / D;

    pk_detect<<<1, 64>>>(idx);
    pk_wot<<<dim3(8, 8), 256>>>(Wout);
    pk1<<<NH * 256, 256>>>(Wq, Wkv);
    pk_pack<<<dim3(32, 8), 256>>>();
    pk2<<<NH * NC, 256>>>(pos);
    pk3<<<NH * 256, 256>>>(Wkv);
    pk4<<<NH * NC, 256>>>(pos);
    pk_par<<<N / 8, 256>>>(parent);
    gemm_k<0><<<dim3(N / 64, 9), 256>>>(nullptr, nullptr);
    attn_k<<<N, 256>>>(child, idx);
    gemm_k<1><<<dim3(N / 64, 2), 256>>>(parent, bout);
    ln_k<<<N / 8, 256>>>(gamma, beta, out);
}

// round 5
// speedup vs baseline: 1.1555x; 1.1206x over previous
#include <cuda_runtime.h>
#include <cuda_bf16.h>
#include <stdint.h>

#define D 256
#define NC 32
#define NH 4
#define C1C 1152
#define NMAX 16384

// ---------------- static device scratch --------------------------------------
__device__ float         g_Af32[NH * 256 * 256];   // scaled A_h fp32  [hj][i]
__device__ float         g_Bf32[1024 * 256];       // Bv fp32          [hj][o]
__device__ float         g_WoT [256 * 256];        // Wout^T           [j][o]
__device__ __nv_bfloat16 g_Abf[256 * C1C];         // GEMM1 weights [K=256][1152]
__device__ __nv_bfloat16 g_Bbf[C1C * 256];         // GEMM2 weights [K=1152][256]
__device__ __nv_bfloat16 g_Pbf[(size_t)NMAX * D];  // parent in bf16
__device__ __nv_bfloat16 g_C1[(size_t)NMAX * C1C]; // GEMM1 out (qW|qP)
__device__ __nv_bfloat16 g_U [(size_t)NMAX * C1C]; // attention out (u|pw)
__device__ int           g_is64;

// ---------------- helpers ----------------------------------------------------
__device__ __forceinline__ unsigned smaddr(const void* p) {
    return (unsigned)__cvta_generic_to_shared(p);
}
__device__ __forceinline__ void ldsm4(uint32_t* r, unsigned a) {
    asm volatile("ldmatrix.sync.aligned.m8n8.x4.shared.b16 {%0,%1,%2,%3}, [%4];"
                 : "=r"(r[0]), "=r"(r[1]), "=r"(r[2]), "=r"(r[3]) : "r"(a));
}
__device__ __forceinline__ void ldsm4t(uint32_t* r, unsigned a) {
    asm volatile("ldmatrix.sync.aligned.m8n8.x4.trans.shared.b16 {%0,%1,%2,%3}, [%4];"
                 : "=r"(r[0]), "=r"(r[1]), "=r"(r[2]), "=r"(r[3]) : "r"(a));
}
__device__ __forceinline__ void mma16816(float* c, const uint32_t* a, const uint32_t* b) {
    asm volatile(
        "mma.sync.aligned.m16n8k16.row.col.f32.bf16.bf16.f32 "
        "{%0,%1,%2,%3},{%4,%5,%6,%7},{%8,%9},{%0,%1,%2,%3};"
        : "+f"(c[0]), "+f"(c[1]), "+f"(c[2]), "+f"(c[3])
        : "r"(a[0]), "r"(a[1]), "r"(a[2]), "r"(a[3]), "r"(b[0]), "r"(b[1]));
}
__device__ __forceinline__ void cpasync16(unsigned dst, const void* src) {
    asm volatile("cp.async.cg.shared.global [%0], [%1], 16;" :: "r"(dst), "l"(src));
}
__device__ __forceinline__ float4 ld4bf(const __nv_bfloat16* p) {
    __nv_bfloat162 x = *(const __nv_bfloat162*)p;
    __nv_bfloat162 y = *(const __nv_bfloat162*)(p + 2);
    return make_float4(__low2float(x), __high2float(x), __low2float(y), __high2float(y));
}

// ---------------- fused precompute 1: detect + Wout^T + A_h ------------------
__device__ void d_detect(const unsigned* __restrict__ idx) {
    __shared__ int any;
    if (threadIdx.x == 0) any = 0;
    __syncthreads();
    if (threadIdx.x < 64 && idx[2 * threadIdx.x + 1] != 0u) any = 1;
    __syncthreads();
    if (threadIdx.x == 0) g_is64 = any ? 0 : 1;
}
__device__ void d_wot(const float* __restrict__ W, int q) {
    __shared__ float tl[32][33];
    int x0 = (q & 7) * 32, y0 = (q >> 3) * 32;
    int tx = threadIdx.x & 31, ty = threadIdx.x >> 5;
#pragma unroll
    for (int k = 0; k < 4; k++) tl[ty + 8 * k][tx] = W[(y0 + ty + 8 * k) * 256 + x0 + tx];
    __syncthreads();
#pragma unroll
    for (int k = 0; k < 4; k++) g_WoT[(x0 + ty + 8 * k) * 256 + y0 + tx] = tl[tx][ty + 8 * k];
}
__device__ void d_pk1(const float* __restrict__ Wq, const float* __restrict__ Wkv, int q) {
    int h = q >> 8, j = q & 255, i = threadIdx.x;
    __shared__ float wk[64];
    if (i < 64) wk[i] = Wkv[(h * 64 + i) * 256 + j];
    __syncthreads();
    float acc = 0.f;
#pragma unroll 8
    for (int dk = 0; dk < 64; dk++) acc += wk[dk] * Wq[(h * 64 + dk) * 256 + i];
    g_Af32[(h * 256 + j) * 256 + i] = acc * 0.125f;
}
__global__ __launch_bounds__(256) void pre1(const float* __restrict__ Wout,
                                            const float* __restrict__ Wq,
                                            const float* __restrict__ Wkv,
                                            const unsigned* __restrict__ idx) {
    int bx = blockIdx.x;
    if (bx == 0)      d_detect(idx);
    else if (bx < 65) d_wot(Wout, bx - 1);
    else              d_pk1(Wq, Wkv, bx - 65);
}

// ---------------- fused precompute 2: pack + qP + Bv + parent-bf16 -----------
__device__ void d_pack(int q) {
    __shared__ float tl[32][33];
    int hj0 = (q & 31) * 32, i0 = (q >> 5) * 32;
    int tx = threadIdx.x & 31, ty = threadIdx.x >> 5;
#pragma unroll
    for (int k = 0; k < 4; k++) tl[ty + 8 * k][tx] = g_Af32[(hj0 + ty + 8 * k) * 256 + i0 + tx];
    __syncthreads();
#pragma unroll
    for (int k = 0; k < 4; k++)
        g_Abf[(size_t)(i0 + ty + 8 * k) * C1C + hj0 + tx] = __float2bfloat16_rn(tl[tx][ty + 8 * k]);
}
__device__ void d_pk2(const float* __restrict__ pos, int q) {
    int h = q >> 5, c = q & 31, i = threadIdx.x;
    __shared__ float pe[256];
    pe[i] = pos[c * 256 + i];
    __syncthreads();
    float acc = 0.f;
#pragma unroll 8
    for (int j = 0; j < 256; j++) acc += g_Af32[(h * 256 + j) * 256 + i] * pe[j];
    g_Abf[(size_t)i * C1C + 1024 + h * 32 + c] = __float2bfloat16_rn(acc);
}
__device__ void d_pk3(const float* __restrict__ Wkv, int q) {
    int h = q >> 8, j = q & 255, o = threadIdx.x;
    __shared__ float wk[64];
    if (o < 64) wk[o] = Wkv[(256 + h * 64 + o) * 256 + j];
    __syncthreads();
    float acc = 0.f;
#pragma unroll 8
    for (int dk = 0; dk < 64; dk++) acc += g_WoT[(h * 64 + dk) * 256 + o] * wk[dk];
    g_Bf32[(h * 256 + j) * 256 + o] = acc;
    g_Bbf[(size_t)(h * 256 + j) * 256 + o] = __float2bfloat16_rn(acc);
}
__device__ void d_par(const float* __restrict__ p, int q) {
    int i = q * 256 + threadIdx.x;
    float4 a = ((const float4*)p)[2 * i], b = ((const float4*)p)[2 * i + 1];
    union { __nv_bfloat162 h[4]; uint4 v; } u;
    u.h[0] = __floats2bfloat162_rn(a.x, a.y);
    u.h[1] = __floats2bfloat162_rn(a.z, a.w);
    u.h[2] = __floats2bfloat162_rn(b.x, b.y);
    u.h[3] = __floats2bfloat162_rn(b.z, b.w);
    ((uint4*)g_Pbf)[i] = u.v;
}
__global__ __launch_bounds__(256) void pre2(const float* __restrict__ pos,
                                            const float* __restrict__ Wkv,
                                            const float* __restrict__ parent) {
    int bx = blockIdx.x;
    if (bx < 256)       d_pack(bx);
    else if (bx < 384)  d_pk2(pos, bx - 256);
    else if (bx < 1408) d_pk3(Wkv, bx - 384);
    else                d_par(parent, bx - 1408);
}
// pk4 must run after pk3 (reads g_Bf32) — separate launch, deferred after attn
__global__ __launch_bounds__(256) void pk4(const float* __restrict__ pos) {
    int h = blockIdx.x >> 5, c = blockIdx.x & 31, o = threadIdx.x;
    __shared__ float pe[256];
    pe[o] = pos[c * 256 + o];
    __syncthreads();
    float acc = 0.f;
#pragma unroll 8
    for (int j = 0; j < 256; j++) acc += pe[j] * g_Bf32[(h * 256 + j) * 256 + o];
    g_Bbf[(size_t)(1024 + h * 32 + c) * 256 + o] = __float2bfloat16_rn(acc);
}

// ---------------- GEMM1: C1[N,1152] = g_Pbf @ g_Abf (64x128 tile) ------------
__global__ __launch_bounds__(256) void gemm1_k() {
    __shared__ __nv_bfloat16 Asm[64][72];
    __shared__ __nv_bfloat16 Bsm[64][136];
    int t = threadIdx.x, lane = t & 31, warp = t >> 5;
    int m0 = blockIdx.x * 64, n0 = blockIdx.y * 128;
    int wm = (warp >> 2) * 32, wn = (warp & 3) * 32;
    float acc[2][4][4];
#pragma unroll
    for (int a = 0; a < 2; a++)
#pragma unroll
        for (int b = 0; b < 4; b++)
#pragma unroll
            for (int c = 0; c < 4; c++) acc[a][b][c] = 0.f;
    uint4 pa[2], pb[4];
#pragma unroll
    for (int it = 0; it < 2; it++) {
        int lin = it * 256 + t, r = lin >> 3, c8 = lin & 7;
        pa[it] = *(const uint4*)(g_Pbf + (size_t)(m0 + r) * 256 + c8 * 8);
    }
#pragma unroll
    for (int it = 0; it < 4; it++) {
        int lin = it * 256 + t, r = lin >> 4, c8 = lin & 15;
        pb[it] = *(const uint4*)(g_Abf + (size_t)r * C1C + n0 + c8 * 8);
    }
    for (int kc = 0; kc < 4; kc++) {
#pragma unroll
        for (int it = 0; it < 2; it++) {
            int lin = it * 256 + t, r = lin >> 3, c8 = lin & 7;
            *(uint4*)&Asm[r][c8 * 8] = pa[it];
        }
#pragma unroll
        for (int it = 0; it < 4; it++) {
            int lin = it * 256 + t, r = lin >> 4, c8 = lin & 15;
            *(uint4*)&Bsm[r][c8 * 8] = pb[it];
        }
        __syncthreads();
        if (kc < 3) {
#pragma unroll
            for (int it = 0; it < 2; it++) {
                int lin = it * 256 + t, r = lin >> 3, c8 = lin & 7;
                pa[it] = *(const uint4*)(g_Pbf + (size_t)(m0 + r) * 256 + (kc + 1) * 64 + c8 * 8);
            }
#pragma unroll
            for (int it = 0; it < 4; it++) {
                int lin = it * 256 + t, r = lin >> 4, c8 = lin & 15;
                pb[it] = *(const uint4*)(g_Abf + (size_t)((kc + 1) * 64 + r) * C1C + n0 + c8 * 8);
            }
        }
#pragma unroll
        for (int ks = 0; ks < 4; ks++) {
            uint32_t af[2][4], bfr[2][4];
#pragma unroll
            for (int mi = 0; mi < 2; mi++)
                ldsm4(af[mi], smaddr(&Asm[wm + mi * 16 + (lane & 15)][ks * 16 + (lane >> 4) * 8]));
#pragma unroll
            for (int nj = 0; nj < 2; nj++)
                ldsm4t(bfr[nj], smaddr(&Bsm[ks * 16 + (lane & 15)][wn + nj * 16 + (lane >> 4) * 8]));
#pragma unroll
            for (int mi = 0; mi < 2; mi++)
#pragma unroll
                for (int nn = 0; nn < 4; nn++)
                    mma16816(acc[mi][nn], af[mi], &bfr[nn >> 1][(nn & 1) * 2]);
        }
        __syncthreads();
    }
#pragma unroll
    for (int mi = 0; mi < 2; mi++)
#pragma unroll
        for (int nn = 0; nn < 4; nn++) {
            int r = m0 + wm + mi * 16 + (lane >> 2);
            int c = n0 + wn + nn * 8 + (lane & 3) * 2;
            float* a = acc[mi][nn];
            *(__nv_bfloat162*)&g_C1[(size_t)r * C1C + c] = __floats2bfloat162_rn(a[0], a[1]);
            *(__nv_bfloat162*)&g_C1[(size_t)(r + 8) * C1C + c] = __floats2bfloat162_rn(a[2], a[3]);
        }
}

// ---------------- attention: row-major smem, conflict-free -------------------
__global__ __launch_bounds__(256) void attn_k(const float* __restrict__ child,
                                              const unsigned* __restrict__ idx) {
    __shared__ float  ch[32 * 256];   // row-major child
    __shared__ float  qp[128];
    __shared__ float4 att4s[32];
    __shared__ float  pw[128];
    __shared__ int    idxs[32];
    float* sc = (float*)att4s;
    int b = blockIdx.x, t = threadIdx.x, lane = t & 31, w = t >> 5;

    // async copy child tile (32KB, straight copy)
    unsigned chb = smaddr(ch);
    const float4* src = (const float4*)(child + (size_t)b * NC * D);
#pragma unroll
    for (int it = 0; it < 8; it++) {
        int lin = it * 256 + t;
        cpasync16(chb + lin * 16, src + lin);
    }
    asm volatile("cp.async.commit_group;");

    if (t < 32) {
        unsigned raw = g_is64 ? idx[(size_t)(b * 32 + t) * 2] : idx[b * 32 + t];
        idxs[t] = (int)(raw & 31u);
    }
    if (t < 128) {
        pw[t] = 0.f;
        qp[t] = __bfloat162float(g_C1[(size_t)b * C1C + 1024 + t]);
    }
    // per-lane qW registers: d in [4l,4l+4) and [128+4l,128+4l+4), 4 heads
    const __nv_bfloat16* c1 = g_C1 + (size_t)b * C1C;
    float4 qA[4], qB[4];
#pragma unroll
    for (int h = 0; h < 4; h++) {
        qA[h] = ld4bf(c1 + h * 256 + 4 * lane);
        qB[h] = ld4bf(c1 + h * 256 + 128 + 4 * lane);
    }
    asm volatile("cp.async.wait_group 0;");
    __syncthreads();

    // phase 1: scores. warp w handles children n = 4w..4w+3
    const float4* ch4 = (const float4*)ch;
#pragma unroll
    for (int p = 0; p < 4; p++) {
        int n = w * 4 + p;
        float4 f0 = ch4[n * 64 + lane];
        float4 f1 = ch4[n * 64 + 32 + lane];
        float a[4];
#pragma unroll
        for (int h = 0; h < 4; h++)
            a[h] = f0.x * qA[h].x + f0.y * qA[h].y + f0.z * qA[h].z + f0.w * qA[h].w +
                   f1.x * qB[h].x + f1.y * qB[h].y + f1.z * qB[h].z + f1.w * qB[h].w;
#pragma unroll
        for (int o = 16; o > 0; o >>= 1) {
#pragma unroll
            for (int h = 0; h < 4; h++) a[h] += __shfl_xor_sync(0xffffffffu, a[h], o);
        }
        if (lane == 0) {
            int c = idxs[n];
            att4s[n] = make_float4(a[0] + qp[c], a[1] + qp[32 + c],
                                   a[2] + qp[64 + c], a[3] + qp[96 + c]);
        }
    }
    __syncthreads();
    // phase 2: softmax over n per head (warp h, lane n), pw scatter
    if (t < 128) {
        int h = t >> 5, n = t & 31;
        float s = sc[n * 4 + h];
        float m = s;
#pragma unroll
        for (int o = 16; o > 0; o >>= 1) m = fmaxf(m, __shfl_xor_sync(0xffffffffu, m, o));
        float e = __expf(s - m);
        float su = e;
#pragma unroll
        for (int o = 16; o > 0; o >>= 1) su += __shfl_xor_sync(0xffffffffu, su, o);
        float a = e / su;
        sc[n * 4 + h] = a;
        atomicAdd(&pw[h * 32 + idxs[n]], a);
    }
    __syncthreads();
    // phase 3: u[h][d] = sum_n att[n][h]*child[n][d]  (thread = d, row-major reads)
    {
        int d = t;
        float u0 = 0.f, u1 = 0.f, u2 = 0.f, u3 = 0.f;
#pragma unroll 8
        for (int n = 0; n < 32; n++) {
            float c = ch[n * 256 + d];
            float4 a = att4s[n];
            u0 += c * a.x; u1 += c * a.y; u2 += c * a.z; u3 += c * a.w;
        }
        __nv_bfloat16* Ub = g_U + (size_t)b * C1C;
        Ub[0 * 256 + d] = __float2bfloat16_rn(u0);
        Ub[1 * 256 + d] = __float2bfloat16_rn(u1);
        Ub[2 * 256 + d] = __float2bfloat16_rn(u2);
        Ub[3 * 256 + d] = __float2bfloat16_rn(u3);
        if (t < 128) Ub[1024 + t] = __float2bfloat16_rn(pw[t]);
    }
}

// ---------------- GEMM2 + fused bias/residual/LayerNorm ----------------------
// out[N,256] = LN( g_U[N,1152] @ g_Bbf + bout + parent )
__global__ __launch_bounds__(256) void gemm2_k(const float* __restrict__ parent,
                                               const float* __restrict__ bias,
                                               const float* __restrict__ gamma,
                                               const float* __restrict__ beta,
                                               float* __restrict__ out) {
    __shared__ __nv_bfloat16 Asm[64][72];
    __shared__ __nv_bfloat16 Bsm[64][264];
    __shared__ float redS[4][64], redSS[4][64];
    int t = threadIdx.x, lane = t & 31, warp = t >> 5;
    int m0 = blockIdx.x * 64;
    int wm = (warp >> 2) * 32, wn = (warp & 3) * 64;
    float acc[2][8][4];
#pragma unroll
    for (int a = 0; a < 2; a++)
#pragma unroll
        for (int b = 0; b < 8; b++)
#pragma unroll
            for (int c = 0; c < 4; c++) acc[a][b][c] = 0.f;

    uint4 pa[2], pb[8];
#pragma unroll
    for (int it = 0; it < 2; it++) {
        int lin = it * 256 + t, r = lin >> 3, c8 = lin & 7;
        pa[it] = *(const uint4*)(g_U + (size_t)(m0 + r) * C1C + c8 * 8);
    }
#pragma unroll
    for (int it = 0; it < 8; it++) {
        int lin = it * 256 + t, r = lin >> 5, c16 = lin & 31;
        pb[it] = *(const uint4*)(g_Bbf + (size_t)r * 256 + c16 * 8);
    }
    for (int kc = 0; kc < 18; kc++) {
#pragma unroll
        for (int it = 0; it < 2; it++) {
            int lin = it * 256 + t, r = lin >> 3, c8 = lin & 7;
            *(uint4*)&Asm[r][c8 * 8] = pa[it];
        }
#pragma unroll
        for (int it = 0; it < 8; it++) {
            int lin = it * 256 + t, r = lin >> 5, c16 = lin & 31;
            *(uint4*)&Bsm[r][c16 * 8] = pb[it];
        }
        __syncthreads();
        if (kc < 17) {
#pragma unroll
            for (int it = 0; it < 2; it++) {
                int lin = it * 256 + t, r = lin >> 3, c8 = lin & 7;
                pa[it] = *(const uint4*)(g_U + (size_t)(m0 + r) * C1C + (kc + 1) * 64 + c8 * 8);
            }
#pragma unroll
            for (int it = 0; it < 8; it++) {
                int lin = it * 256 + t, r = lin >> 5, c16 = lin & 31;
                pb[it] = *(const uint4*)(g_Bbf + (size_t)((kc + 1) * 64 + r) * 256 + c16 * 8);
            }
        }
#pragma unroll
        for (int ks = 0; ks < 4; ks++) {
            uint32_t af[2][4], bfr[4][4];
#pragma unroll
            for (int mi = 0; mi < 2; mi++)
                ldsm4(af[mi], smaddr(&Asm[wm + mi * 16 + (lane & 15)][ks * 16 + (lane >> 4) * 8]));
#pragma unroll
            for (int nj = 0; nj < 4; nj++)
                ldsm4t(bfr[nj], smaddr(&Bsm[ks * 16 + (lane & 15)][wn + nj * 16 + (lane >> 4) * 8]));
#pragma unroll
            for (int mi = 0; mi < 2; mi++)
#pragma unroll
                for (int nn = 0; nn < 8; nn++)
                    mma16816(acc[mi][nn], af[mi], &bfr[nn >> 1][(nn & 1) * 2]);
        }
        __syncthreads();
    }
    // epilogue: bias + residual, per-row LN stats
    float s[4] = {0.f, 0.f, 0.f, 0.f}, ss[4] = {0.f, 0.f, 0.f, 0.f};
#pragma unroll
    for (int mi = 0; mi < 2; mi++) {
        int r0 = wm + mi * 16 + (lane >> 2);
#pragma unroll
        for (int nn = 0; nn < 8; nn++) {
            int c = wn + nn * 8 + (lane & 3) * 2;
            float b0 = bias[c], b1 = bias[c + 1];
            float2 p0 = *(const float2*)(parent + (size_t)(m0 + r0) * 256 + c);
            float2 p1 = *(const float2*)(parent + (size_t)(m0 + r0 + 8) * 256 + c);
            float* a = acc[mi][nn];
            a[0] += b0 + p0.x; a[1] += b1 + p0.y;
            a[2] += b0 + p1.x; a[3] += b1 + p1.y;
            s[mi * 2 + 0] += a[0] + a[1]; ss[mi * 2 + 0] += a[0] * a[0] + a[1] * a[1];
            s[mi * 2 + 1] += a[2] + a[3]; ss[mi * 2 + 1] += a[2] * a[2] + a[3] * a[3];
        }
    }
#pragma unroll
    for (int o = 1; o <= 2; o <<= 1) {
#pragma unroll
        for (int i = 0; i < 4; i++) {
            s[i]  += __shfl_xor_sync(0xffffffffu, s[i], o);
            ss[i] += __shfl_xor_sync(0xffffffffu, ss[i], o);
        }
    }
    if ((lane & 3) == 0) {
#pragma unroll
        for (int mi = 0; mi < 2; mi++)
#pragma unroll
            for (int hf = 0; hf < 2; hf++) {
                int lr = wm + mi * 16 + (lane >> 2) + hf * 8;
                redS[warp & 3][lr]  = s[mi * 2 + hf];
                redSS[warp & 3][lr] = ss[mi * 2 + hf];
            }
    }
    __syncthreads();
#pragma unroll
    for (int mi = 0; mi < 2; mi++) {
#pragma unroll
        for (int hf = 0; hf < 2; hf++) {
            int lr = wm + mi * 16 + (lane >> 2) + hf * 8;
            float S  = redS[0][lr] + redS[1][lr] + redS[2][lr] + redS[3][lr];
            float SS = redSS[0][lr] + redSS[1][lr] + redSS[2][lr] + redSS[3][lr];
            float mu = S * (1.0f / 256.0f);
            float var = SS * (1.0f / 256.0f) - mu * mu;
            float rs = rsqrtf(var + 1e-5f);
#pragma unroll
            for (int nn = 0; nn < 8; nn++) {
                int c = wn + nn * 8 + (lane & 3) * 2;
                float v0 = acc[mi][nn][hf * 2 + 0], v1 = acc[mi][nn][hf * 2 + 1];
                *(float2*)(out + (size_t)(m0 + lr) * 256 + c) =
                    make_float2((v0 - mu) * rs * gamma[c] + beta[c],
                                (v1 - mu) * rs * gamma[c + 1] + beta[c + 1]);
            }
        }
    }
}

// ---------------- launch -----------------------------------------------------
extern "C" void kernel_launch(void* const* d_in, const int* in_sizes, int n_in,
                              void* d_out, int out_size) {
    const float*    parent = (const float*)d_in[0];
    const float*    child  = (const float*)d_in[1];
    const unsigned* idx    = (const unsigned*)d_in[2];
    const float*    Wq     = (const float*)d_in[3];
    const float*    Wkv    = (const float*)d_in[4];
    const float*    pos    = (const float*)d_in[5];
    const float*    Wout   = (const float*)d_in[6];
    const float*    bout   = (const float*)d_in[7];
    const float*    gamma  = (const float*)d_in[8];
    const float*    beta   = (const float*)d_in[9];
    float* out = (float*)d_out;
    int N = in_sizes[0] / D;

    pre1<<<1089, 256>>>(Wout, Wq, Wkv, idx);
    pre2<<<1408 + N / 8, 256>>>(pos, Wkv, parent);
    gemm1_k<<<dim3(N / 64, 9), 256>>>();
    attn_k<<<N, 256>>>(child, idx);            // 4th launch -> ncu profiles this
    pk4<<<128, 256>>>(pos);
    gemm2_k<<<N / 64, 256>>>(parent, bout, gamma, beta, out);
}